// round 15
// baseline (speedup 1.0000x reference)
#include <cuda_runtime.h>
#include <cuda_bf16.h>
#include <cuda_fp16.h>
#include <cstdint>
#include <math.h>

#define NT  4096
#define DD  1024
#define HFd 2048
#define HSd 4096
#define NE  8
#define NF  4

// ---------------- routing state ----------------
__device__ int   g_cnt[NE];
__device__ int   g_te[NT][2];
__device__ int   g_ts[NT][2];
__device__ float g_tw[NT][2];

// ---------------- scratch layout (bytes) ----------------
constexpr size_t B_XGH = 0;                                   // [NE][NT][DD]
constexpr size_t B_XGL = B_XGH + (size_t)NE * NT * DD * 2;    // fractal lo (combine)
constexpr size_t B_WF1H = B_XGL + (size_t)NE * NT * DD * 2;
constexpr size_t SZ_WF = (size_t)NF * HFd * DD * 2;
constexpr size_t B_WF3H = B_WF1H + SZ_WF;
constexpr size_t B_WF2H = B_WF3H + SZ_WF;
constexpr size_t SZ_WS = (size_t)4 * HSd * DD * 2;
constexpr size_t B_WS1H = B_WF2H + SZ_WF;
constexpr size_t B_WS3H = B_WS1H + SZ_WS;
constexpr size_t B_WS2H = B_WS3H + SZ_WS;
constexpr size_t B_HFH  = B_WS2H + SZ_WS;                     // frac act bf16
constexpr size_t B_HSH  = B_HFH + (size_t)NF * NT * HFd * 2;  // switch act fp16
constexpr size_t B_Y    = B_HSH + (size_t)4 * NT * HSd * 2;   // fp32
constexpr size_t SCRATCH_BYTES = B_Y + (size_t)NE * NT * DD * 4;
__device__ __align__(1024) unsigned char g_scratch[SCRATCH_BYTES];

// ---------------- PTX helpers ----------------
__device__ __forceinline__ uint32_t smem_u32(const void* p) {
    uint32_t a;
    asm("{ .reg .u64 t; cvta.to.shared.u64 t, %1; cvt.u32.u64 %0, t; }" : "=r"(a) : "l"(p));
    return a;
}
__device__ __forceinline__ uint64_t gbl_u64(const void* p) {
    uint64_t a;
    asm("cvta.to.global.u64 %0, %1;" : "=l"(a) : "l"(p));
    return a;
}
__device__ __forceinline__ void cpa16(uint32_t s, uint64_t g) {
    asm volatile("cp.async.cg.shared.global [%0], [%1], 16;" :: "r"(s), "l"(g) : "memory");
}
__device__ __forceinline__ void cpa_commit() {
    asm volatile("cp.async.commit_group;" ::: "memory");
}
template<int N>
__device__ __forceinline__ void cpa_wait() {
    asm volatile("cp.async.wait_group %0;" :: "n"(N) : "memory");
}
__device__ __forceinline__ void ldm4(uint32_t* r, uint32_t addr) {
    asm volatile("ldmatrix.sync.aligned.m8n8.x4.shared.b16 {%0,%1,%2,%3}, [%4];"
        : "=r"(r[0]), "=r"(r[1]), "=r"(r[2]), "=r"(r[3]) : "r"(addr));
}
__device__ __forceinline__ void mma_bf16(float* d, const uint32_t* a, uint32_t b0, uint32_t b1) {
    asm volatile("mma.sync.aligned.m16n8k16.row.col.f32.bf16.bf16.f32 "
        "{%0,%1,%2,%3}, {%4,%5,%6,%7}, {%8,%9}, {%0,%1,%2,%3};"
        : "+f"(d[0]), "+f"(d[1]), "+f"(d[2]), "+f"(d[3])
        : "r"(a[0]), "r"(a[1]), "r"(a[2]), "r"(a[3]), "r"(b0), "r"(b1));
}
__device__ __forceinline__ void mma_fp16(float* d, const uint32_t* a, uint32_t b0, uint32_t b1) {
    asm volatile("mma.sync.aligned.m16n8k16.row.col.f32.f16.f16.f32 "
        "{%0,%1,%2,%3}, {%4,%5,%6,%7}, {%8,%9}, {%0,%1,%2,%3};"
        : "+f"(d[0]), "+f"(d[1]), "+f"(d[2]), "+f"(d[3])
        : "r"(a[0]), "r"(a[1]), "r"(a[2]), "r"(a[3]), "r"(b0), "r"(b1));
}
__device__ __forceinline__ uint32_t pack_bf2(float x, float y) {
    union { __nv_bfloat162 h; uint32_t u; } c;
    c.h = __float22bfloat162_rn(make_float2(x, y));
    return c.u;
}
__device__ __forceinline__ float2 unpack_bf2(uint32_t u) {
    union { uint32_t v; __nv_bfloat162 h; } c; c.v = u;
    return __bfloat1622float2(c.h);
}
__device__ __forceinline__ uint32_t pack_h2(float x, float y) {
    union { __half2 h; uint32_t u; } c;
    c.h = __float22half2_rn(make_float2(x, y));
    return c.u;
}
__device__ __forceinline__ float silu(float a) { return a / (1.f + expf(-a)); }

// ---------------- reset counts ----------------
__global__ void reset_cnt() {
    if (threadIdx.x < NE) g_cnt[threadIdx.x] = 0;
}

// ---------------- fused router + gather (block per token) ----------------
__global__ void __launch_bounds__(256) router_gather(
    const float* __restrict__ x, const float* __restrict__ rw,
    const float* __restrict__ frms)
{
    const int t = blockIdx.x;
    const int tid = threadIdx.x;
    const int lane = tid & 31;
    const int wid = tid >> 5;

    __shared__ float xrow[DD];
    __shared__ float slog[NE];
    __shared__ float sred[8];
    __shared__ int   s_e[2], s_s[2];

    float4 v = ((const float4*)(x + (size_t)t * DD))[tid];
    *(float4*)&xrow[tid * 4] = v;
    // sum of squares (for fractal rmsnorm)
    float ss = v.x * v.x + v.y * v.y + v.z * v.z + v.w * v.w;
#pragma unroll
    for (int o = 16; o; o >>= 1) ss += __shfl_xor_sync(0xffffffffu, ss, o);
    if (lane == 0) sred[wid] = ss;
    __syncthreads();

    // 8 warps: warp e computes logit e
    {
        const float* wr = rw + (size_t)wid * DD;
        float s = 0.f;
        for (int d = lane; d < DD; d += 32) s = fmaf(xrow[d], wr[d], s);
#pragma unroll
        for (int o = 16; o; o >>= 1) s += __shfl_xor_sync(0xffffffffu, s, o);
        if (lane == 0) slog[wid] = s;
    }
    __syncthreads();

    if (tid == 0) {
        float l[NE];
#pragma unroll
        for (int e = 0; e < NE; e++) l[e] = slog[e];
        float m = l[0];
#pragma unroll
        for (int e = 1; e < NE; e++) m = fmaxf(m, l[e]);
        float w[NE], sum = 0.f;
#pragma unroll
        for (int e = 0; e < NE; e++) { w[e] = expf(l[e] - m); sum += w[e]; }
        float inv = 1.f / sum;
#pragma unroll
        for (int e = 0; e < NE; e++) w[e] *= inv;
        int i1 = 0;
#pragma unroll
        for (int e = 1; e < NE; e++) if (w[e] > w[i1]) i1 = e;
        int i2 = (i1 == 0) ? 1 : 0;
#pragma unroll
        for (int e = 0; e < NE; e++) if (e != i1 && w[e] > w[i2]) i2 = e;
        float tw = fmaxf(w[i1] + w[i2], 1e-9f);
        int p1 = atomicAdd(&g_cnt[i1], 1);
        int p2 = atomicAdd(&g_cnt[i2], 1);
        g_te[t][0] = i1; g_ts[t][0] = p1; g_tw[t][0] = w[i1] / tw;
        g_te[t][1] = i2; g_ts[t][1] = p2; g_tw[t][1] = w[i2] / tw;
        s_e[0] = i1; s_s[0] = p1;
        s_e[1] = i2; s_s[1] = p2;
        float r = 0.f;
#pragma unroll
        for (int q = 0; q < 8; q++) r += sred[q];
        sred[0] = rsqrtf(r * (1.f / DD) + 1e-6f);
    }
    __syncthreads();

    const float scale = sred[0];
#pragma unroll
    for (int k = 0; k < 2; k++) {
        int e = s_e[k];
        int s = s_s[k];
        size_t base = ((size_t)e * NT + s) * DD + (size_t)tid * 4;
        if (e < NF) {
            float4 g = ((const float4*)(frms + (size_t)e * DD))[tid];
            float o0 = v.x * scale * g.x, o1 = v.y * scale * g.y;
            float o2 = v.z * scale * g.z, o3 = v.w * scale * g.w;
            uint32_t h0 = pack_bf2(o0, o1), h1 = pack_bf2(o2, o3);
            float2 f0 = unpack_bf2(h0), f1 = unpack_bf2(h1);
            uint32_t l0 = pack_bf2(o0 - f0.x, o1 - f0.y), l1 = pack_bf2(o2 - f1.x, o3 - f1.y);
            *(uint2*)((__nv_bfloat16*)(g_scratch + B_XGH) + base) = make_uint2(h0, h1);
            *(uint2*)((__nv_bfloat16*)(g_scratch + B_XGL) + base) = make_uint2(l0, l1);
        } else {
            uint32_t h0 = pack_h2(v.x, v.y), h1 = pack_h2(v.z, v.w);
            *(uint2*)((__nv_bfloat16*)(g_scratch + B_XGH) + base) = make_uint2(h0, h1);
        }
    }
}

// ---------------- weight conversions (side stream) ----------------
__global__ void conv_up(const float* __restrict__ fw1, const float* __restrict__ fw3,
                        const float* __restrict__ sw1, const float* __restrict__ sw3) {
    int z = blockIdx.y;
    size_t i = ((size_t)blockIdx.x * 256u + threadIdx.x) * 8;
    if (z < 2 && i >= SZ_WF / 2) return;
    const float* src = (z == 0) ? fw1 : (z == 1) ? fw3 : (z == 2) ? sw1 : sw3;
    size_t offH = (z == 0) ? B_WF1H : (z == 1) ? B_WF3H : (z == 2) ? B_WS1H : B_WS3H;
    float4 v0 = *(const float4*)(src + i);
    float4 v1 = *(const float4*)(src + i + 4);
    uint4 H;
    if (z < 2)
        H = make_uint4(pack_bf2(v0.x, v0.y), pack_bf2(v0.z, v0.w),
                       pack_bf2(v1.x, v1.y), pack_bf2(v1.z, v1.w));
    else
        H = make_uint4(pack_h2(v0.x, v0.y), pack_h2(v0.z, v0.w),
                       pack_h2(v1.x, v1.y), pack_h2(v1.z, v1.w));
    *(uint4*)((__nv_bfloat16*)(g_scratch + offH) + i) = H;
}
__global__ void conv_down(const float* __restrict__ fw2, const float* __restrict__ sw2) {
    int z = blockIdx.y;
    size_t i = ((size_t)blockIdx.x * 256u + threadIdx.x) * 8;
    if (z == 0 && i >= SZ_WF / 2) return;
    const float* src = (z == 0) ? fw2 : sw2;
    size_t offH = (z == 0) ? B_WF2H : B_WS2H;
    float4 v0 = *(const float4*)(src + i);
    float4 v1 = *(const float4*)(src + i + 4);
    uint4 H;
    if (z == 0)
        H = make_uint4(pack_bf2(v0.x, v0.y), pack_bf2(v0.z, v0.w),
                       pack_bf2(v1.x, v1.y), pack_bf2(v1.z, v1.w));
    else
        H = make_uint4(pack_h2(v0.x, v0.y), pack_h2(v0.z, v0.w),
                       pack_h2(v1.x, v1.y), pack_h2(v1.z, v1.w));
    *(uint4*)((__nv_bfloat16*)(g_scratch + offH) + i) = H;
}

// ---------------- cp.async multi-stage tensor-core GEMM body ----------------
// 128 threads, 4 warps (2 m x 2 n), warp tile 64x64.
// CTA: 128x128 (FUSE=0) or 128x(64 gate + 64 val) (FUSE=1).
// smem rows: 64B, XOR swizzle; 16KB stage x 6 -> 96KB/CTA -> 2 CTAs/SM.
#define SROW    64
#define APLANE  8192u
#define STG     16384u
#define STAGES  6

template<int DT, int FUSE>
__device__ __forceinline__ void gemm_body(
    const __nv_bfloat16* __restrict__ A,
    const __nv_bfloat16* __restrict__ B0,
    const __nv_bfloat16* __restrict__ B1,
    float* __restrict__ Cf, __nv_bfloat16* __restrict__ Hh,
    int cnt, int m0, int n0, int K, int Nn, char* smem)
{
    const uint32_t sb = smem_u32(smem);
    const int tid  = threadIdx.x;
    const int lane = tid & 31;
    const int wid  = tid >> 5;
    const int mr   = wid & 1;    // 2 m-warps of 64 rows
    const int nc   = wid >> 1;   // 2 n-warps of 64 B-rows

    // staging: thread -> row tid (one 64B row of A and of B), 4 granules each
    const int row = tid;
    const int xorS = (row >> 1) & 3;
    const uint64_t gA = gbl_u64(A + (size_t)(m0 + row) * K);
    const int browg = FUSE ? ((row < 64) ? (n0 + row) : (n0 + row - 64)) : (n0 + row);
    const __nv_bfloat16* BSrc = (FUSE && row >= 64) ? B1 : B0;
    const uint64_t gB = gbl_u64(BSrc + (size_t)browg * K);
    uint32_t sAo[4], sBo[4];
#pragma unroll
    for (int c = 0; c < 4; c++) {
        sAo[c] = (uint32_t)row * SROW + (uint32_t)((c ^ xorS) * 16);
        sBo[c] = APLANE + sAo[c];
    }

    const int xorA = (lane >> 1) & 3;
    const int bnoff = (lane & 7) + ((lane >> 4) << 3);
    const int xorB = (bnoff >> 1) & 3;
    const uint32_t aRowOff = (uint32_t)(mr * 64 + (lane & 15)) * SROW;
    const int aCol = lane >> 4;
    const int bCol = (lane >> 3) & 1;

    float acc[4][8][4];
#pragma unroll
    for (int i = 0; i < 4; i++)
#pragma unroll
        for (int j = 0; j < 8; j++)
#pragma unroll
            for (int q = 0; q < 4; q++) acc[i][j][q] = 0.f;

    const int nst = K >> 5;

    auto issue = [&](int kc, uint32_t base) {
        uint64_t d = (uint64_t)kc * 64;
#pragma unroll
        for (int c = 0; c < 4; c++) {
            cpa16(base + sAo[c], gA + d + c * 16);
            cpa16(base + sBo[c], gB + d + c * 16);
        }
    };

#pragma unroll
    for (int s = 0; s < STAGES - 1; s++) {
        issue(s, sb + (uint32_t)s * STG);
        cpa_commit();
    }

    int slot = 0, wslot = STAGES - 1;
    for (int kc = 0; kc < nst; kc++) {
        cpa_wait<STAGES - 2>();
        __syncthreads();
        const int knext = kc + STAGES - 1;
        if (knext < nst) issue(knext, sb + (uint32_t)wslot * STG);
        cpa_commit();

        const uint32_t base = sb + (uint32_t)slot * STG;
#pragma unroll
        for (int k16 = 0; k16 < 2; k16++) {
            const uint32_t ca = (uint32_t)(((aCol + 2 * k16) ^ xorA) * 16);
            const uint32_t cb = (uint32_t)(((bCol + 2 * k16) ^ xorB) * 16);
            uint32_t ah[4][4];
#pragma unroll
            for (int mt = 0; mt < 4; mt++)
                ldm4(ah[mt], base + aRowOff + (uint32_t)(mt * 16) * SROW + ca);
#pragma unroll
            for (int np = 0; np < 4; np++) {
                const uint32_t brow = FUSE
                    ? (uint32_t)((np < 2) ? (nc * 32 + np * 16) : (64 + nc * 32 + (np - 2) * 16))
                    : (uint32_t)(nc * 64 + np * 16);
                uint32_t bh[4];
                ldm4(bh, base + APLANE + (brow + (uint32_t)bnoff) * SROW + cb);
#pragma unroll
                for (int mt = 0; mt < 4; mt++)
#pragma unroll
                    for (int s2 = 0; s2 < 2; s2++) {
                        float* d = acc[mt][np * 2 + s2];
                        if (DT == 1) mma_fp16(d, ah[mt], bh[2 * s2], bh[2 * s2 + 1]);
                        else         mma_bf16(d, ah[mt], bh[2 * s2], bh[2 * s2 + 1]);
                    }
            }
        }
        slot = (slot + 1 < STAGES) ? slot + 1 : 0;
        wslot = (wslot + 1 < STAGES) ? wslot + 1 : 0;
    }

    if (FUSE == 0) {
#pragma unroll
        for (int mt = 0; mt < 4; mt++) {
            int r0 = m0 + mr * 64 + mt * 16 + (lane >> 2);
#pragma unroll
            for (int j = 0; j < 8; j++) {
                int col = n0 + nc * 64 + j * 8 + 2 * (lane & 3);
                if (r0 < cnt)
                    *(float2*)(Cf + (size_t)r0 * Nn + col) = make_float2(acc[mt][j][0], acc[mt][j][1]);
                if (r0 + 8 < cnt)
                    *(float2*)(Cf + (size_t)(r0 + 8) * Nn + col) = make_float2(acc[mt][j][2], acc[mt][j][3]);
            }
        }
    } else {
#pragma unroll
        for (int mt = 0; mt < 4; mt++) {
            int r0 = m0 + mr * 64 + mt * 16 + (lane >> 2);
#pragma unroll
            for (int j = 0; j < 4; j++) {
                int col = n0 + nc * 32 + j * 8 + 2 * (lane & 3);
#pragma unroll
                for (int hh = 0; hh < 2; hh++) {
                    int r = r0 + hh * 8;
                    if (r < cnt) {
                        float h0 = silu(acc[mt][j][2 * hh])     * acc[mt][j + 4][2 * hh];
                        float h1 = silu(acc[mt][j][2 * hh + 1]) * acc[mt][j + 4][2 * hh + 1];
                        uint32_t hp = (DT == 1) ? pack_h2(h0, h1) : pack_bf2(h0, h1);
                        *(uint32_t*)(Hh + (size_t)r * Nn + col) = hp;
                    }
                }
            }
        }
    }
}

// ---------------- merged up kernel ----------------
__global__ void __launch_bounds__(128, 2) up_kernel() {
    extern __shared__ char smem[];
    const int z = blockIdx.z;
    const int m0 = blockIdx.y * 128;
    if (z < NF) {
        if (blockIdx.x >= HFd / 64) return;
        const int e = z;
        const int cnt = g_cnt[e];
        if (m0 >= cnt) return;
        const int n0 = blockIdx.x * 64;
        const __nv_bfloat16* A = (const __nv_bfloat16*)(g_scratch + B_XGH) + (size_t)e * NT * DD;
        const __nv_bfloat16* W1 = (const __nv_bfloat16*)(g_scratch + B_WF1H) + (size_t)e * HFd * DD;
        const __nv_bfloat16* W3 = (const __nv_bfloat16*)(g_scratch + B_WF3H) + (size_t)e * HFd * DD;
        __nv_bfloat16* Hh = (__nv_bfloat16*)(g_scratch + B_HFH) + (size_t)e * NT * HFd;
        gemm_body<0, 1>(A, W1, W3, nullptr, Hh, cnt, m0, n0, DD, HFd, smem);
    } else {
        const int e = z - NF;
        const int cnt = g_cnt[NF + e];
        if (m0 >= cnt) return;
        const int n0 = blockIdx.x * 64;
        const __nv_bfloat16* A = (const __nv_bfloat16*)(g_scratch + B_XGH) + (size_t)(NF + e) * NT * DD;
        const __nv_bfloat16* W1 = (const __nv_bfloat16*)(g_scratch + B_WS1H) + (size_t)e * HSd * DD;
        const __nv_bfloat16* W3 = (const __nv_bfloat16*)(g_scratch + B_WS3H) + (size_t)e * HSd * DD;
        __nv_bfloat16* Hh = (__nv_bfloat16*)(g_scratch + B_HSH) + (size_t)e * NT * HSd;
        gemm_body<1, 1>(A, W1, W3, nullptr, Hh, cnt, m0, n0, DD, HSd, smem);
    }
}

// ---------------- merged down kernel ----------------
__global__ void __launch_bounds__(128, 2) down_kernel() {
    extern __shared__ char smem[];
    const int z = blockIdx.z;
    const int m0 = blockIdx.y * 128;
    const int n0 = blockIdx.x * 128;
    if (z < NF) {
        const int e = z;
        const int cnt = g_cnt[e];
        if (m0 >= cnt) return;
        const __nv_bfloat16* H = (const __nv_bfloat16*)(g_scratch + B_HFH) + (size_t)e * NT * HFd;
        const __nv_bfloat16* W2 = (const __nv_bfloat16*)(g_scratch + B_WF2H) + (size_t)e * DD * HFd;
        float* Y = (float*)(g_scratch + B_Y) + (size_t)e * NT * DD;
        gemm_body<0, 0>(H, W2, W2, Y, nullptr, cnt, m0, n0, HFd, DD, smem);
    } else {
        const int e = z - NF;
        const int cnt = g_cnt[NF + e];
        if (m0 >= cnt) return;
        const __nv_bfloat16* H = (const __nv_bfloat16*)(g_scratch + B_HSH) + (size_t)e * NT * HSd;
        const __nv_bfloat16* W2 = (const __nv_bfloat16*)(g_scratch + B_WS2H) + (size_t)e * DD * HSd;
        float* Y = (float*)(g_scratch + B_Y) + (size_t)(NF + e) * NT * DD;
        gemm_body<1, 0>(H, W2, W2, Y, nullptr, cnt, m0, n0, HSd, DD, smem);
    }
}

// ---------------- final combine ----------------
__global__ void combine_kernel(const float* __restrict__ x, const float* __restrict__ gamma,
                               float* __restrict__ out) {
    size_t idx = (size_t)blockIdx.x * 256u + threadIdx.x;
    int t = (int)(idx >> 8);
    int d = (int)(idx & 255) * 4;
    float4 xv = ((const float4*)x)[idx];
    float4 res = make_float4(0.f, 0.f, 0.f, 0.f);
#pragma unroll
    for (int k = 0; k < 2; k++) {
        int e = g_te[t][k];
        int s = g_ts[t][k];
        float w = g_tw[t][k];
        size_t base = ((size_t)e * NT + s) * DD + d;
        float4 y = *(const float4*)((const float*)(g_scratch + B_Y) + base);
        float4 val;
        if (e < NF) {
            uint2 hu = *(const uint2*)((const __nv_bfloat16*)(g_scratch + B_XGH) + base);
            uint2 lu = *(const uint2*)((const __nv_bfloat16*)(g_scratch + B_XGL) + base);
            float2 h0 = unpack_bf2(hu.x), h1 = unpack_bf2(hu.y);
            float2 l0 = unpack_bf2(lu.x), l1 = unpack_bf2(lu.y);
            float4 g = *(const float4*)(gamma + (size_t)e * DD + d);
            val.x = g.x * (h0.x + l0.x + y.x) + xv.x;
            val.y = g.y * (h0.y + l0.y + y.y) + xv.y;
            val.z = g.z * (h1.x + l1.x + y.z) + xv.z;
            val.w = g.w * (h1.y + l1.y + y.w) + xv.w;
        } else {
            val = y;
        }
        res.x += w * val.x; res.y += w * val.y;
        res.z += w * val.z; res.w += w * val.w;
    }
    ((float4*)out)[idx] = res;
}

// ---------------- launch ----------------
extern "C" void kernel_launch(void* const* d_in, const int* in_sizes, int n_in,
                              void* d_out, int out_size) {
    const float* x          = (const float*)d_in[0];
    const float* router_w   = (const float*)d_in[1];
    const float* frac_rms   = (const float*)d_in[2];
    const float* frac_w1    = (const float*)d_in[3];
    const float* frac_w2    = (const float*)d_in[4];
    const float* frac_w3    = (const float*)d_in[5];
    const float* frac_gamma = (const float*)d_in[6];
    const float* sw_w1      = (const float*)d_in[7];
    const float* sw_w2      = (const float*)d_in[8];
    const float* sw_w3      = (const float*)d_in[9];
    float* out = (float*)d_out;
    (void)in_sizes; (void)n_in; (void)out_size;

    constexpr int SMX = STAGES * (int)STG;   // 98304 per CTA, 2 CTAs/SM
    cudaFuncSetAttribute(up_kernel, cudaFuncAttributeMaxDynamicSharedMemorySize, SMX);
    cudaFuncSetAttribute(down_kernel, cudaFuncAttributeMaxDynamicSharedMemorySize, SMX);

    cudaStream_t s2;
    cudaStreamCreateWithFlags(&s2, cudaStreamNonBlocking);
    cudaEvent_t evRoot, evConv1, evConv2;
    cudaEventCreateWithFlags(&evRoot, cudaEventDisableTiming);
    cudaEventCreateWithFlags(&evConv1, cudaEventDisableTiming);
    cudaEventCreateWithFlags(&evConv2, cudaEventDisableTiming);

    cudaEventRecord(evRoot, 0);
    cudaStreamWaitEvent(s2, evRoot, 0);
    conv_up<<<dim3((int)(SZ_WS / 2 / 2048), 4), 256, 0, s2>>>(frac_w1, frac_w3, sw_w1, sw_w3);
    cudaEventRecord(evConv1, s2);
    conv_down<<<dim3((int)(SZ_WS / 2 / 2048), 2), 256, 0, s2>>>(frac_w2, sw_w2);
    cudaEventRecord(evConv2, s2);

    reset_cnt<<<1, 32>>>();
    router_gather<<<NT, 256>>>(x, router_w, frac_rms);

    cudaStreamWaitEvent(0, evConv1, 0);
    up_kernel<<<dim3(HSd / 64, NT / 128, NF + 4), 128, SMX>>>();
    cudaStreamWaitEvent(0, evConv2, 0);
    down_kernel<<<dim3(DD / 128, NT / 128, NF + 4), 128, SMX>>>();
    combine_kernel<<<(NT * DD / 4) / 256, 256>>>(x, frac_gamma, out);

    cudaEventDestroy(evRoot);
    cudaEventDestroy(evConv1);
    cudaEventDestroy(evConv2);
    cudaStreamDestroy(s2);
}

// round 16
// speedup vs baseline: 1.3835x; 1.3835x over previous
#include <cuda_runtime.h>
#include <cuda_bf16.h>
#include <cuda_fp16.h>
#include <cstdint>
#include <math.h>

#define NT  4096
#define DD  1024
#define HFd 2048
#define HSd 4096
#define NE  8
#define NF  4

// ---------------- routing state ----------------
__device__ int   g_cnt[NE];
__device__ int   g_te[NT][2];
__device__ int   g_ts[NT][2];
__device__ float g_tw[NT][2];

// ---------------- scratch layout (bytes) ----------------
constexpr size_t B_XGH = 0;                                   // [NE][NT][DD]
constexpr size_t B_XGL = B_XGH + (size_t)NE * NT * DD * 2;    // fractal lo (combine)
constexpr size_t B_WF1H = B_XGL + (size_t)NE * NT * DD * 2;
constexpr size_t SZ_WF = (size_t)NF * HFd * DD * 2;
constexpr size_t B_WF3H = B_WF1H + SZ_WF;
constexpr size_t B_WF2H = B_WF3H + SZ_WF;
constexpr size_t SZ_WS = (size_t)4 * HSd * DD * 2;
constexpr size_t B_WS1H = B_WF2H + SZ_WF;
constexpr size_t B_WS3H = B_WS1H + SZ_WS;
constexpr size_t B_WS2H = B_WS3H + SZ_WS;
constexpr size_t B_HFH  = B_WS2H + SZ_WS;                     // frac act bf16
constexpr size_t B_HSH  = B_HFH + (size_t)NF * NT * HFd * 2;  // switch act fp16
constexpr size_t B_Y    = B_HSH + (size_t)4 * NT * HSd * 2;   // fp32
constexpr size_t SCRATCH_BYTES = B_Y + (size_t)NE * NT * DD * 4;
__device__ __align__(1024) unsigned char g_scratch[SCRATCH_BYTES];

// ---------------- PTX helpers ----------------
__device__ __forceinline__ uint32_t smem_u32(const void* p) {
    uint32_t a;
    asm("{ .reg .u64 t; cvta.to.shared.u64 t, %1; cvt.u32.u64 %0, t; }" : "=r"(a) : "l"(p));
    return a;
}
__device__ __forceinline__ uint64_t gbl_u64(const void* p) {
    uint64_t a;
    asm("cvta.to.global.u64 %0, %1;" : "=l"(a) : "l"(p));
    return a;
}
__device__ __forceinline__ void cpa16(uint32_t s, uint64_t g) {
    asm volatile("cp.async.cg.shared.global [%0], [%1], 16;" :: "r"(s), "l"(g) : "memory");
}
__device__ __forceinline__ void cpa_commit() {
    asm volatile("cp.async.commit_group;" ::: "memory");
}
template<int N>
__device__ __forceinline__ void cpa_wait() {
    asm volatile("cp.async.wait_group %0;" :: "n"(N) : "memory");
}
__device__ __forceinline__ void ldm4(uint32_t* r, uint32_t addr) {
    asm volatile("ldmatrix.sync.aligned.m8n8.x4.shared.b16 {%0,%1,%2,%3}, [%4];"
        : "=r"(r[0]), "=r"(r[1]), "=r"(r[2]), "=r"(r[3]) : "r"(addr));
}
__device__ __forceinline__ void mma_bf16(float* d, const uint32_t* a, uint32_t b0, uint32_t b1) {
    asm volatile("mma.sync.aligned.m16n8k16.row.col.f32.bf16.bf16.f32 "
        "{%0,%1,%2,%3}, {%4,%5,%6,%7}, {%8,%9}, {%0,%1,%2,%3};"
        : "+f"(d[0]), "+f"(d[1]), "+f"(d[2]), "+f"(d[3])
        : "r"(a[0]), "r"(a[1]), "r"(a[2]), "r"(a[3]), "r"(b0), "r"(b1));
}
__device__ __forceinline__ void mma_fp16(float* d, const uint32_t* a, uint32_t b0, uint32_t b1) {
    asm volatile("mma.sync.aligned.m16n8k16.row.col.f32.f16.f16.f32 "
        "{%0,%1,%2,%3}, {%4,%5,%6,%7}, {%8,%9}, {%0,%1,%2,%3};"
        : "+f"(d[0]), "+f"(d[1]), "+f"(d[2]), "+f"(d[3])
        : "r"(a[0]), "r"(a[1]), "r"(a[2]), "r"(a[3]), "r"(b0), "r"(b1));
}
__device__ __forceinline__ uint32_t pack_bf2(float x, float y) {
    union { __nv_bfloat162 h; uint32_t u; } c;
    c.h = __float22bfloat162_rn(make_float2(x, y));
    return c.u;
}
__device__ __forceinline__ float2 unpack_bf2(uint32_t u) {
    union { uint32_t v; __nv_bfloat162 h; } c; c.v = u;
    return __bfloat1622float2(c.h);
}
__device__ __forceinline__ uint32_t pack_h2(float x, float y) {
    union { __half2 h; uint32_t u; } c;
    c.h = __float22half2_rn(make_float2(x, y));
    return c.u;
}
__device__ __forceinline__ float silu(float a) { return a / (1.f + expf(-a)); }

// ---------------- reset counts ----------------
__global__ void reset_cnt() {
    if (threadIdx.x < NE) g_cnt[threadIdx.x] = 0;
}

// ---------------- fused router + gather (block per token) ----------------
__global__ void __launch_bounds__(256) router_gather(
    const float* __restrict__ x, const float* __restrict__ rw,
    const float* __restrict__ frms)
{
    const int t = blockIdx.x;
    const int tid = threadIdx.x;
    const int lane = tid & 31;
    const int wid = tid >> 5;

    __shared__ float xrow[DD];
    __shared__ float slog[NE];
    __shared__ float sred[8];
    __shared__ int   s_e[2], s_s[2];

    float4 v = ((const float4*)(x + (size_t)t * DD))[tid];
    *(float4*)&xrow[tid * 4] = v;
    float ss = v.x * v.x + v.y * v.y + v.z * v.z + v.w * v.w;
#pragma unroll
    for (int o = 16; o; o >>= 1) ss += __shfl_xor_sync(0xffffffffu, ss, o);
    if (lane == 0) sred[wid] = ss;
    __syncthreads();

    {
        const float* wr = rw + (size_t)wid * DD;
        float s = 0.f;
        for (int d = lane; d < DD; d += 32) s = fmaf(xrow[d], wr[d], s);
#pragma unroll
        for (int o = 16; o; o >>= 1) s += __shfl_xor_sync(0xffffffffu, s, o);
        if (lane == 0) slog[wid] = s;
    }
    __syncthreads();

    if (tid == 0) {
        float l[NE];
#pragma unroll
        for (int e = 0; e < NE; e++) l[e] = slog[e];
        float m = l[0];
#pragma unroll
        for (int e = 1; e < NE; e++) m = fmaxf(m, l[e]);
        float w[NE], sum = 0.f;
#pragma unroll
        for (int e = 0; e < NE; e++) { w[e] = expf(l[e] - m); sum += w[e]; }
        float inv = 1.f / sum;
#pragma unroll
        for (int e = 0; e < NE; e++) w[e] *= inv;
        int i1 = 0;
#pragma unroll
        for (int e = 1; e < NE; e++) if (w[e] > w[i1]) i1 = e;
        int i2 = (i1 == 0) ? 1 : 0;
#pragma unroll
        for (int e = 0; e < NE; e++) if (e != i1 && w[e] > w[i2]) i2 = e;
        float tw = fmaxf(w[i1] + w[i2], 1e-9f);
        int p1 = atomicAdd(&g_cnt[i1], 1);
        int p2 = atomicAdd(&g_cnt[i2], 1);
        g_te[t][0] = i1; g_ts[t][0] = p1; g_tw[t][0] = w[i1] / tw;
        g_te[t][1] = i2; g_ts[t][1] = p2; g_tw[t][1] = w[i2] / tw;
        s_e[0] = i1; s_s[0] = p1;
        s_e[1] = i2; s_s[1] = p2;
        float r = 0.f;
#pragma unroll
        for (int q = 0; q < 8; q++) r += sred[q];
        sred[0] = rsqrtf(r * (1.f / DD) + 1e-6f);
    }
    __syncthreads();

    const float scale = sred[0];
#pragma unroll
    for (int k = 0; k < 2; k++) {
        int e = s_e[k];
        int s = s_s[k];
        size_t base = ((size_t)e * NT + s) * DD + (size_t)tid * 4;
        if (e < NF) {
            float4 g = ((const float4*)(frms + (size_t)e * DD))[tid];
            float o0 = v.x * scale * g.x, o1 = v.y * scale * g.y;
            float o2 = v.z * scale * g.z, o3 = v.w * scale * g.w;
            uint32_t h0 = pack_bf2(o0, o1), h1 = pack_bf2(o2, o3);
            float2 f0 = unpack_bf2(h0), f1 = unpack_bf2(h1);
            uint32_t l0 = pack_bf2(o0 - f0.x, o1 - f0.y), l1 = pack_bf2(o2 - f1.x, o3 - f1.y);
            *(uint2*)((__nv_bfloat16*)(g_scratch + B_XGH) + base) = make_uint2(h0, h1);
            *(uint2*)((__nv_bfloat16*)(g_scratch + B_XGL) + base) = make_uint2(l0, l1);
        } else {
            uint32_t h0 = pack_h2(v.x, v.y), h1 = pack_h2(v.z, v.w);
            *(uint2*)((__nv_bfloat16*)(g_scratch + B_XGH) + base) = make_uint2(h0, h1);
        }
    }
}

// ---------------- weight conversions (side stream) ----------------
__global__ void conv_up(const float* __restrict__ fw1, const float* __restrict__ fw3,
                        const float* __restrict__ sw1, const float* __restrict__ sw3) {
    int z = blockIdx.y;
    size_t i = ((size_t)blockIdx.x * 256u + threadIdx.x) * 8;
    if (z < 2 && i >= SZ_WF / 2) return;
    const float* src = (z == 0) ? fw1 : (z == 1) ? fw3 : (z == 2) ? sw1 : sw3;
    size_t offH = (z == 0) ? B_WF1H : (z == 1) ? B_WF3H : (z == 2) ? B_WS1H : B_WS3H;
    float4 v0 = *(const float4*)(src + i);
    float4 v1 = *(const float4*)(src + i + 4);
    uint4 H;
    if (z < 2)
        H = make_uint4(pack_bf2(v0.x, v0.y), pack_bf2(v0.z, v0.w),
                       pack_bf2(v1.x, v1.y), pack_bf2(v1.z, v1.w));
    else
        H = make_uint4(pack_h2(v0.x, v0.y), pack_h2(v0.z, v0.w),
                       pack_h2(v1.x, v1.y), pack_h2(v1.z, v1.w));
    *(uint4*)((__nv_bfloat16*)(g_scratch + offH) + i) = H;
}
__global__ void conv_down(const float* __restrict__ fw2, const float* __restrict__ sw2) {
    int z = blockIdx.y;
    size_t i = ((size_t)blockIdx.x * 256u + threadIdx.x) * 8;
    if (z == 0 && i >= SZ_WF / 2) return;
    const float* src = (z == 0) ? fw2 : sw2;
    size_t offH = (z == 0) ? B_WF2H : B_WS2H;
    float4 v0 = *(const float4*)(src + i);
    float4 v1 = *(const float4*)(src + i + 4);
    uint4 H;
    if (z == 0)
        H = make_uint4(pack_bf2(v0.x, v0.y), pack_bf2(v0.z, v0.w),
                       pack_bf2(v1.x, v1.y), pack_bf2(v1.z, v1.w));
    else
        H = make_uint4(pack_h2(v0.x, v0.y), pack_h2(v0.z, v0.w),
                       pack_h2(v1.x, v1.y), pack_h2(v1.z, v1.w));
    *(uint4*)((__nv_bfloat16*)(g_scratch + offH) + i) = H;
}

// ---------------- cp.async multi-stage tensor-core GEMM body ----------------
// 256 threads, 8 warps (4 m x 2 n), warp tile 32x64 (R14-proven shape).
// CTA: 128x128 (FUSE=0) or 128x(64 gate + 64 val) (FUSE=1).
// smem rows: 64B, XOR swizzle col16 ^= (row>>1)&3; 16KB stage x 6 -> 96KB/CTA, 2 CTAs/SM.
#define SROW    64
#define APLANE  8192u
#define STG     16384u
#define STAGES  6

template<int DT, int FUSE>
__device__ __forceinline__ void gemm_body(
    const __nv_bfloat16* __restrict__ A,
    const __nv_bfloat16* __restrict__ B0,
    const __nv_bfloat16* __restrict__ B1,
    float* __restrict__ Cf, __nv_bfloat16* __restrict__ Hh,
    int cnt, int m0, int n0, int K, int Nn, char* smem)
{
    const uint32_t sb = smem_u32(smem);
    const int tid  = threadIdx.x;
    const int lane = tid & 31;
    const int wid  = tid >> 5;
    const int mr   = wid & 3;
    const int nc   = wid >> 2;

    const int row = tid >> 1;
    const int g2  = (tid & 1) * 2;
    const int xorS = (row >> 1) & 3;
    const uint64_t gA = gbl_u64(A + (size_t)(m0 + row) * K + g2 * 8);
    const int browg = FUSE ? ((row < 64) ? (n0 + row) : (n0 + row - 64)) : (n0 + row);
    const __nv_bfloat16* BSrc = (FUSE && row >= 64) ? B1 : B0;
    const uint64_t gB = gbl_u64(BSrc + (size_t)browg * K + g2 * 8);
    const uint32_t sA0 = (uint32_t)row * SROW + (uint32_t)((g2 ^ xorS) * 16);
    const uint32_t sA1 = (uint32_t)row * SROW + (uint32_t)(((g2 + 1) ^ xorS) * 16);
    const uint32_t sB0 = APLANE + sA0;
    const uint32_t sB1 = APLANE + sA1;

    const int xorA = (lane >> 1) & 3;
    const int bnoff = (lane & 7) + ((lane >> 4) << 3);
    const int xorB = (bnoff >> 1) & 3;
    const uint32_t aRowOff = (uint32_t)(mr * 32 + (lane & 15)) * SROW;
    const int aCol = lane >> 4;
    const int bCol = (lane >> 3) & 1;

    float acc[2][8][4];
#pragma unroll
    for (int i = 0; i < 2; i++)
#pragma unroll
        for (int j = 0; j < 8; j++)
#pragma unroll
            for (int q = 0; q < 4; q++) acc[i][j][q] = 0.f;

    const int nst = K >> 5;

    auto issue = [&](int kc, uint32_t base) {
        uint64_t d = (uint64_t)kc * 64;
        cpa16(base + sA0, gA + d);      cpa16(base + sA1, gA + d + 16);
        cpa16(base + sB0, gB + d);      cpa16(base + sB1, gB + d + 16);
    };

#pragma unroll
    for (int s = 0; s < STAGES - 1; s++) {
        issue(s, sb + (uint32_t)s * STG);
        cpa_commit();
    }

    int slot = 0, wslot = STAGES - 1;
    for (int kc = 0; kc < nst; kc++) {
        cpa_wait<STAGES - 2>();
        __syncthreads();
        const int knext = kc + STAGES - 1;
        if (knext < nst) issue(knext, sb + (uint32_t)wslot * STG);
        cpa_commit();

        const uint32_t base = sb + (uint32_t)slot * STG;
#pragma unroll
        for (int k16 = 0; k16 < 2; k16++) {
            const uint32_t ca = (uint32_t)(((aCol + 2 * k16) ^ xorA) * 16);
            const uint32_t cb = (uint32_t)(((bCol + 2 * k16) ^ xorB) * 16);
            uint32_t ah[2][4];
#pragma unroll
            for (int mt = 0; mt < 2; mt++)
                ldm4(ah[mt], base + aRowOff + (uint32_t)(mt * 16) * SROW + ca);
#pragma unroll
            for (int np = 0; np < 4; np++) {
                const uint32_t brow = FUSE
                    ? (uint32_t)((np < 2) ? (nc * 32 + np * 16) : (64 + nc * 32 + (np - 2) * 16))
                    : (uint32_t)(nc * 64 + np * 16);
                uint32_t bh[4];
                ldm4(bh, base + APLANE + (brow + (uint32_t)bnoff) * SROW + cb);
#pragma unroll
                for (int mt = 0; mt < 2; mt++)
#pragma unroll
                    for (int s2 = 0; s2 < 2; s2++) {
                        float* d = acc[mt][np * 2 + s2];
                        if (DT == 1) mma_fp16(d, ah[mt], bh[2 * s2], bh[2 * s2 + 1]);
                        else         mma_bf16(d, ah[mt], bh[2 * s2], bh[2 * s2 + 1]);
                    }
            }
        }
        slot = (slot + 1 < STAGES) ? slot + 1 : 0;
        wslot = (wslot + 1 < STAGES) ? wslot + 1 : 0;
    }

    if (FUSE == 0) {
#pragma unroll
        for (int mt = 0; mt < 2; mt++) {
            int r0 = m0 + mr * 32 + mt * 16 + (lane >> 2);
#pragma unroll
            for (int j = 0; j < 8; j++) {
                int col = n0 + nc * 64 + j * 8 + 2 * (lane & 3);
                if (r0 < cnt)
                    *(float2*)(Cf + (size_t)r0 * Nn + col) = make_float2(acc[mt][j][0], acc[mt][j][1]);
                if (r0 + 8 < cnt)
                    *(float2*)(Cf + (size_t)(r0 + 8) * Nn + col) = make_float2(acc[mt][j][2], acc[mt][j][3]);
            }
        }
    } else {
#pragma unroll
        for (int mt = 0; mt < 2; mt++) {
            int r0 = m0 + mr * 32 + mt * 16 + (lane >> 2);
#pragma unroll
            for (int j = 0; j < 4; j++) {
                int col = n0 + nc * 32 + j * 8 + 2 * (lane & 3);
#pragma unroll
                for (int hh = 0; hh < 2; hh++) {
                    int r = r0 + hh * 8;
                    if (r < cnt) {
                        float h0 = silu(acc[mt][j][2 * hh])     * acc[mt][j + 4][2 * hh];
                        float h1 = silu(acc[mt][j][2 * hh + 1]) * acc[mt][j + 4][2 * hh + 1];
                        uint32_t hp = (DT == 1) ? pack_h2(h0, h1) : pack_bf2(h0, h1);
                        *(uint32_t*)(Hh + (size_t)r * Nn + col) = hp;
                    }
                }
            }
        }
    }
}

// ---------------- merged up kernel ----------------
__global__ void __launch_bounds__(256, 2) up_kernel() {
    extern __shared__ char smem[];
    const int z = blockIdx.z;
    const int m0 = blockIdx.y * 128;
    if (z < NF) {
        if (blockIdx.x >= HFd / 64) return;
        const int e = z;
        const int cnt = g_cnt[e];
        if (m0 >= cnt) return;
        const int n0 = blockIdx.x * 64;
        const __nv_bfloat16* A = (const __nv_bfloat16*)(g_scratch + B_XGH) + (size_t)e * NT * DD;
        const __nv_bfloat16* W1 = (const __nv_bfloat16*)(g_scratch + B_WF1H) + (size_t)e * HFd * DD;
        const __nv_bfloat16* W3 = (const __nv_bfloat16*)(g_scratch + B_WF3H) + (size_t)e * HFd * DD;
        __nv_bfloat16* Hh = (__nv_bfloat16*)(g_scratch + B_HFH) + (size_t)e * NT * HFd;
        gemm_body<0, 1>(A, W1, W3, nullptr, Hh, cnt, m0, n0, DD, HFd, smem);
    } else {
        const int e = z - NF;
        const int cnt = g_cnt[NF + e];
        if (m0 >= cnt) return;
        const int n0 = blockIdx.x * 64;
        const __nv_bfloat16* A = (const __nv_bfloat16*)(g_scratch + B_XGH) + (size_t)(NF + e) * NT * DD;
        const __nv_bfloat16* W1 = (const __nv_bfloat16*)(g_scratch + B_WS1H) + (size_t)e * HSd * DD;
        const __nv_bfloat16* W3 = (const __nv_bfloat16*)(g_scratch + B_WS3H) + (size_t)e * HSd * DD;
        __nv_bfloat16* Hh = (__nv_bfloat16*)(g_scratch + B_HSH) + (size_t)e * NT * HSd;
        gemm_body<1, 1>(A, W1, W3, nullptr, Hh, cnt, m0, n0, DD, HSd, smem);
    }
}

// ---------------- merged down kernel ----------------
__global__ void __launch_bounds__(256, 2) down_kernel() {
    extern __shared__ char smem[];
    const int z = blockIdx.z;
    const int m0 = blockIdx.y * 128;
    const int n0 = blockIdx.x * 128;
    if (z < NF) {
        const int e = z;
        const int cnt = g_cnt[e];
        if (m0 >= cnt) return;
        const __nv_bfloat16* H = (const __nv_bfloat16*)(g_scratch + B_HFH) + (size_t)e * NT * HFd;
        const __nv_bfloat16* W2 = (const __nv_bfloat16*)(g_scratch + B_WF2H) + (size_t)e * DD * HFd;
        float* Y = (float*)(g_scratch + B_Y) + (size_t)e * NT * DD;
        gemm_body<0, 0>(H, W2, W2, Y, nullptr, cnt, m0, n0, HFd, DD, smem);
    } else {
        const int e = z - NF;
        const int cnt = g_cnt[NF + e];
        if (m0 >= cnt) return;
        const __nv_bfloat16* H = (const __nv_bfloat16*)(g_scratch + B_HSH) + (size_t)e * NT * HSd;
        const __nv_bfloat16* W2 = (const __nv_bfloat16*)(g_scratch + B_WS2H) + (size_t)e * DD * HSd;
        float* Y = (float*)(g_scratch + B_Y) + (size_t)(NF + e) * NT * DD;
        gemm_body<1, 0>(H, W2, W2, Y, nullptr, cnt, m0, n0, HSd, DD, smem);
    }
}

// ---------------- final combine ----------------
__global__ void combine_kernel(const float* __restrict__ x, const float* __restrict__ gamma,
                               float* __restrict__ out) {
    size_t idx = (size_t)blockIdx.x * 256u + threadIdx.x;
    int t = (int)(idx >> 8);
    int d = (int)(idx & 255) * 4;
    float4 xv = ((const float4*)x)[idx];
    float4 res = make_float4(0.f, 0.f, 0.f, 0.f);
#pragma unroll
    for (int k = 0; k < 2; k++) {
        int e = g_te[t][k];
        int s = g_ts[t][k];
        float w = g_tw[t][k];
        size_t base = ((size_t)e * NT + s) * DD + d;
        float4 y = *(const float4*)((const float*)(g_scratch + B_Y) + base);
        float4 val;
        if (e < NF) {
            uint2 hu = *(const uint2*)((const __nv_bfloat16*)(g_scratch + B_XGH) + base);
            uint2 lu = *(const uint2*)((const __nv_bfloat16*)(g_scratch + B_XGL) + base);
            float2 h0 = unpack_bf2(hu.x), h1 = unpack_bf2(hu.y);
            float2 l0 = unpack_bf2(lu.x), l1 = unpack_bf2(lu.y);
            float4 g = *(const float4*)(gamma + (size_t)e * DD + d);
            val.x = g.x * (h0.x + l0.x + y.x) + xv.x;
            val.y = g.y * (h0.y + l0.y + y.y) + xv.y;
            val.z = g.z * (h1.x + l1.x + y.z) + xv.z;
            val.w = g.w * (h1.y + l1.y + y.w) + xv.w;
        } else {
            val = y;
        }
        res.x += w * val.x; res.y += w * val.y;
        res.z += w * val.z; res.w += w * val.w;
    }
    ((float4*)out)[idx] = res;
}

// ---------------- launch ----------------
extern "C" void kernel_launch(void* const* d_in, const int* in_sizes, int n_in,
                              void* d_out, int out_size) {
    const float* x          = (const float*)d_in[0];
    const float* router_w   = (const float*)d_in[1];
    const float* frac_rms   = (const float*)d_in[2];
    const float* frac_w1    = (const float*)d_in[3];
    const float* frac_w2    = (const float*)d_in[4];
    const float* frac_w3    = (const float*)d_in[5];
    const float* frac_gamma = (const float*)d_in[6];
    const float* sw_w1      = (const float*)d_in[7];
    const float* sw_w2      = (const float*)d_in[8];
    const float* sw_w3      = (const float*)d_in[9];
    float* out = (float*)d_out;
    (void)in_sizes; (void)n_in; (void)out_size;

    constexpr int SMX = STAGES * (int)STG;   // 98304 per CTA, 2 CTAs/SM
    cudaFuncSetAttribute(up_kernel, cudaFuncAttributeMaxDynamicSharedMemorySize, SMX);
    cudaFuncSetAttribute(down_kernel, cudaFuncAttributeMaxDynamicSharedMemorySize, SMX);

    cudaStream_t s2;
    cudaStreamCreateWithFlags(&s2, cudaStreamNonBlocking);
    cudaEvent_t evRoot, evConv1, evConv2;
    cudaEventCreateWithFlags(&evRoot, cudaEventDisableTiming);
    cudaEventCreateWithFlags(&evConv1, cudaEventDisableTiming);
    cudaEventCreateWithFlags(&evConv2, cudaEventDisableTiming);

    cudaEventRecord(evRoot, 0);
    cudaStreamWaitEvent(s2, evRoot, 0);
    conv_up<<<dim3((int)(SZ_WS / 2 / 2048), 4), 256, 0, s2>>>(frac_w1, frac_w3, sw_w1, sw_w3);
    cudaEventRecord(evConv1, s2);
    conv_down<<<dim3((int)(SZ_WS / 2 / 2048), 2), 256, 0, s2>>>(frac_w2, sw_w2);
    cudaEventRecord(evConv2, s2);

    reset_cnt<<<1, 32>>>();
    router_gather<<<NT, 256>>>(x, router_w, frac_rms);

    cudaStreamWaitEvent(0, evConv1, 0);
    up_kernel<<<dim3(HSd / 64, NT / 128, NF + 4), 256, SMX>>>();
    cudaStreamWaitEvent(0, evConv2, 0);
    down_kernel<<<dim3(DD / 128, NT / 128, NF + 4), 256, SMX>>>();
    combine_kernel<<<(NT * DD / 4) / 256, 256>>>(x, frac_gamma, out);

    cudaEventDestroy(evRoot);
    cudaEventDestroy(evConv1);
    cudaEventDestroy(evConv2);
    cudaStreamDestroy(s2);
}